// round 13
// baseline (speedup 1.0000x reference)
#include <cuda_runtime.h>

// Problem constants
#define NB 8
#define NT 4096
#define NN 1024
#define NP (NB*NT)      // 32768 points
#define NU 256          // unknown nodes
#define NKMAX 768
#define PTS 32          // points per fused block
#define TPB 1024
#define SROW2 17        // float2 stride per column (32 pts = 16 float2 + 1 pad)
#define DUMMY (NN*SROW2)   // float2-index of zeroed dummy column (fits u16)
#define KCAP 12288      // compact known-CSR cap (u16), pair-padded
#define LCAP 3072       // compact lower-CSR cap (u16), padded to 4

typedef unsigned char  u8;
typedef unsigned short u16;
typedef unsigned int   u32;
typedef unsigned long long ull;

__device__ __forceinline__ void fadd2(ull& a, ull b) {
    asm("add.rn.f32x2 %0, %0, %1;" : "+l"(a) : "l"(b));
}

// ---------------- scratch (device globals; allocation-free) ----------------
__device__ float g_invdeg[NU];
__device__ float g_c[NU];
__device__ int   g_Kcol[NU*NKMAX];
__device__ int   g_Kcnt[NU];
__device__ int   g_Lcol[NU*NU];
__device__ int   g_Lcnt[NU];
__device__ __align__(16) u16 g_Kc[KCAP];   // col*17, dummy-padded
__device__ __align__(16) u16 g_Lc[LCAP];   // unk[rank]*17, dummy-padded
__device__ int   g_Kptr[NU];
__device__ int   g_Nit[NU/2];     // gather iterations (of 4 elems) per pair
__device__ int   g_Lptr[NU+1];
__device__ float g_rhsc[NU];
__device__ int   g_woff[NU];      // unk[i]*17
__device__ int   g_order[NU];
__device__ int   g_lvlptr[NU+1];
__device__ int   g_nlev[1];

// small pack mirrored into __constant__ between k_meta and k_fused
struct KPack { int ktot; int ltot; u8 knownb[NN]; };
__device__    KPack g_kp;
__constant__  KPack c_kp;

// ---------------- launch 0: per-row: deg + padded CSR + c ------------------
// 256 blocks x 256 threads; 8-warp two-pass deterministic compaction.
__global__ void k_row(const float* __restrict__ A, const int* __restrict__ unk) {
    __shared__ float srow[NN];
    __shared__ int   srank[NN];
    __shared__ int   wkc[8], wlc[8], wkoff[8], wloff[8];
    __shared__ float wcc[8], wdd[8];
    int i = blockIdx.x, t = threadIdx.x, w = t >> 5, lane = t & 31;
    for (int n = t; n < NN; n += 256) srank[n] = -1;
    __syncthreads();
    srank[__ldg(&unk[t])] = t;          // t = 0..255 = NU
    int ui = __ldg(&unk[i]);
    const float* row = A + (size_t)ui * NN;
    for (int n = t; n < NN; n += 256) srow[n] = row[n];
    __syncthreads();
    unsigned lt = (1u << lane) - 1u;
    int base0 = w * 128;
    // ---- pass 1: counts + exact sums ----
    int kc = 0, lc = 0; float c = 0.f, d = 0.f;
    #pragma unroll
    for (int r = 0; r < 4; r++) {
        int n = base0 + r*32 + lane;
        float a = srow[n];
        int rk = srank[n];
        bool nz = (a != 0.f);
        d += a;
        unsigned mK = __ballot_sync(0xFFFFFFFFu, nz && rk < 0);
        unsigned mL = __ballot_sync(0xFFFFFFFFu, nz && rk >= 0 && rk < i);
        if (nz && rk >= i) c += a;
        kc += __popc(mK); lc += __popc(mL);
    }
    for (int o = 16; o > 0; o >>= 1) {
        c += __shfl_down_sync(0xFFFFFFFFu, c, o);
        d += __shfl_down_sync(0xFFFFFFFFu, d, o);
    }
    if (lane == 0) { wkc[w] = kc; wlc[w] = lc; wcc[w] = c; wdd[w] = d; }
    __syncthreads();
    if (t == 0) {
        int ka = 0, la = 0; float cc = 0.f, dd = 0.f;
        #pragma unroll
        for (int j = 0; j < 8; j++) {
            wkoff[j] = ka; ka += wkc[j];
            wloff[j] = la; la += wlc[j];
            cc += wcc[j]; dd += wdd[j];       // sums of 0/1: exact, order-free
        }
        g_Kcnt[i] = ka; g_Lcnt[i] = la; g_c[i] = cc;
        g_invdeg[i] = 1.f / dd;
    }
    __syncthreads();
    // ---- pass 2: write with stitched offsets (ascending n preserved) ----
    kc = wkoff[w]; lc = wloff[w];
    #pragma unroll
    for (int r = 0; r < 4; r++) {
        int n = base0 + r*32 + lane;
        float a = srow[n];
        int rk = srank[n];
        bool nz = (a != 0.f);
        unsigned mK = __ballot_sync(0xFFFFFFFFu, nz && rk < 0);
        unsigned mL = __ballot_sync(0xFFFFFFFFu, nz && rk >= 0 && rk < i);
        if (nz) {
            if (rk < 0)      g_Kcol[i*NKMAX + kc + __popc(mK & lt)] = n;
            else if (rk < i) g_Lcol[i*NU    + lc + __popc(mL & lt)] = rk;
        }
        kc += __popc(mK); lc += __popc(mL);
    }
}

// ---------------- launch 1: compact + constants + levels (parallel) --------
__global__ void k_meta(const int* __restrict__ unk, const float* __restrict__ maskp) {
    __shared__ int skcnt[NU], slcnt[NU], sunk[NU];
    __shared__ int pairLen[NU/2], scanA[NU], lp4[NU];
    __shared__ int kptr[NU], lptr[NU+1];
    __shared__ u16 slrank[LCAP];
    __shared__ int lev[NU];
    __shared__ u8  knb[NN];
    __shared__ int changed, smax;
    __shared__ int wsum[8], wsum2[8];
    int t = threadIdx.x, w = t >> 5, lane = t & 31;   // 1024 threads
    knb[t] = 1;
    if (t < NU) { skcnt[t] = g_Kcnt[t]; slcnt[t] = g_Lcnt[t]; sunk[t] = unk[t]; }
    __syncthreads();
    if (t < NU) knb[sunk[t]] = 0;
    __syncthreads();
    g_kp.knownb[t] = knb[t];
    if (t < NU/2) {
        int m = skcnt[2*t] > skcnt[2*t+1] ? skcnt[2*t] : skcnt[2*t+1];
        m = (m + 3) & ~3;
        pairLen[t] = m < 4 ? 4 : m;     // min one quad: prefetch-safe
    }
    if (t < NU) {
        int m = (slcnt[t] + 3) & ~3;
        lp4[t] = m < 4 ? 4 : m;
    }
    __syncthreads();
    // ---- inclusive scan of pairLen (n=128) via shuffles ----
    {
        int sv = 0;
        if (t < 128) {
            sv = pairLen[t];
            #pragma unroll
            for (int off = 1; off < 32; off <<= 1) {
                int u = __shfl_up_sync(0xFFFFFFFFu, sv, off);
                if (lane >= off) sv += u;
            }
            if (lane == 31) wsum[w] = sv;
        }
        __syncthreads();
        if (t < 128) {
            int add = 0;
            for (int j = 0; j < w; j++) add += wsum[j];
            scanA[t] = sv + add;
        }
        __syncthreads();
    }
    if (t < NU) {
        int j = t >> 1;
        kptr[t] = 2*(scanA[j] - pairLen[j]) + (t & 1)*pairLen[j];
    }
    if (t == 0) g_kp.ktot = 2*scanA[NU/2-1] < KCAP ? 2*scanA[NU/2-1] : KCAP;
    __syncthreads();
    // ---- inclusive scan of lp4 (n=256) via shuffles ----
    {
        int sv = 0;
        if (t < NU) {
            sv = lp4[t];
            #pragma unroll
            for (int off = 1; off < 32; off <<= 1) {
                int u = __shfl_up_sync(0xFFFFFFFFu, sv, off);
                if (lane >= off) sv += u;
            }
            if (lane == 31) wsum2[w] = sv;
        }
        __syncthreads();
        if (t < NU) {
            int add = 0;
            for (int j = 0; j < w; j++) add += wsum2[j];
            scanA[t] = sv + add;
        }
        __syncthreads();
    }
    if (t < NU) lptr[t] = scanA[t] - lp4[t];
    if (t == 0) {
        lptr[NU] = scanA[NU-1];
        g_kp.ltot = scanA[NU-1] < LCAP ? scanA[NU-1] : LCAP;
    }
    __syncthreads();
    // ---- compaction: warp per unknown ----
    for (int ii = 0; ii < 8; ii++) {
        int i = w + 32*ii;
        int kb = kptr[i], kc = skcnt[i], kp = pairLen[i >> 1];
        for (int s = lane; s < kp; s += 32) {
            u16 v = (s < kc) ? (u16)(g_Kcol[i*NKMAX + s] * SROW2) : (u16)DUMMY;
            if (kb + s < KCAP) g_Kc[kb + s] = v;
        }
        int lb = lptr[i], lc = slcnt[i], lp = lp4[i];
        for (int s = lane; s < lp; s += 32) {
            u16 v = (u16)DUMMY;
            if (s < lc) {
                int r = g_Lcol[i*NU + s];
                v = (u16)(sunk[r] * SROW2);
                if (lb + s < LCAP) slrank[lb + s] = (u16)r;
            }
            if (lb + s < LCAP) g_Lc[lb + s] = v;
        }
    }
    if (t < NU) {
        g_rhsc[t] = maskp[0] * g_c[t] * g_invdeg[t];
        g_woff[t] = sunk[t] * SROW2;
        g_Kptr[t] = kptr[t];
    }
    if (t < NU/2) g_Nit[t] = pairLen[t] >> 2;
    if (t <= NU) g_Lptr[t] = lptr[t];
    __syncthreads();
    // ---- level fixpoint: 256 threads, named barrier (cheap drain) ----
    if (t < NU) lev[t] = 0;
    __syncthreads();
    if (t < 256) {
        for (int iter = 0; iter < NU; iter++) {
            if (t == 0) changed = 0;
            asm volatile("bar.sync 1, 256;" ::: "memory");
            int nl = 0;
            {
                int b = lptr[t], e = b + slcnt[t];
                if (e > LCAP) e = LCAP;
                for (int s = b; s < e; s++) {
                    int lj = lev[slrank[s]] + 1;
                    nl = nl > lj ? nl : lj;
                }
            }
            asm volatile("bar.sync 1, 256;" ::: "memory");
            if (nl != lev[t]) { lev[t] = nl; changed = 1; }
            asm volatile("bar.sync 1, 256;" ::: "memory");
            if (!changed) break;
        }
    }
    __syncthreads();
    if (t == 0) smax = 0;
    __syncthreads();
    if (t < NU) atomicMax(&smax, lev[t]);
    __syncthreads();
    if (t <= NU) {
        int c = 0;
        for (int j = 0; j < NU; j++) c += (lev[j] < t);
        g_lvlptr[t] = c;
    }
    if (t < NU) {
        int my = lev[t], pos = 0;
        for (int j = 0; j < NU; j++) {
            int lj = lev[j];
            pos += (lj < my) || (lj == my && j < t);
        }
        g_order[pos] = t;
    }
    if (t == 0) g_nlev[0] = smax + 1;
}

// ---------------- launch 2: fused load(known) -> gather -> solve -> copy ---
__global__ void __launch_bounds__(TPB, 1) k_fused(const float* __restrict__ x,
                                                  float* __restrict__ out) {
    extern __shared__ char smraw[];
    float2* sx2   = (float2*)smraw;                      // (NN+1)*17 float2
    char* p = smraw + (((NN+1)*SROW2*sizeof(float2) + 15) & ~15);  // 16B align
    u16*   sKoff = (u16*)p;          p += KCAP*2;        // 16B aligned
    u16*   sLoff = (u16*)p;          p += LCAP*2;
    int*   sKptr = (int*)p;          p += NU*4;
    int*   sNit  = (int*)p;          p += (NU/2)*4;
    int*   sLptr = (int*)p;          p += (NU+1)*4;
    int*   sOrd  = (int*)p;          p += NU*4;
    int*   sLvl  = (int*)p;          p += (NU+1)*4;
    float* sInv  = (float*)p;        p += NU*4;
    float* sRhs  = (float*)p;        p += NU*4;
    int*   sWoff = (int*)p;
    __shared__ int s_nlev;

    int tid = threadIdx.x, lane = tid & 31, w = tid >> 5;
    int h2 = lane >> 4, pl = lane & 15;
    const float* xb = x   + (size_t)blockIdx.x * PTS * NN;
    float*       ob = out + (size_t)blockIdx.x * PTS * NN;

    // ---- kn from constant cache (~30 cyc) so x LDGs issue immediately ----
    int kn = c_kp.knownb[tid];
    int ktot = c_kp.ktot, ltot = c_kp.ltot;

    // ---- batch-1 x LDGs first (longest latency) ----
    float v[16];
    if (kn) {
        #pragma unroll
        for (int q = 0; q < 16; q++) v[q] = xb[(size_t)q*NN + tid];
    }

    // ---- async-stage index arrays (contiguous 16B cp.async) ----
    {
        u32 sk = (u32)__cvta_generic_to_shared(sKoff);
        u32 sl = (u32)__cvta_generic_to_shared(sLoff);
        const char* gk = (const char*)g_Kc;
        const char* gl = (const char*)g_Lc;
        int kb = (ktot*2 + 15) & ~15;
        int lb = (ltot*2 + 15) & ~15;
        for (int o = tid*16; o < kb; o += TPB*16)
            asm volatile("cp.async.ca.shared.global [%0], [%1], 16;"
                         :: "r"(sk + o), "l"(gk + o));
        for (int o = tid*16; o < lb; o += TPB*16)
            asm volatile("cp.async.ca.shared.global [%0], [%1], 16;"
                         :: "r"(sl + o), "l"(gl + o));
        asm volatile("cp.async.commit_group;");
    }
    // ---- scalar metadata (hides batch-1 latency) ----
    if (tid < NU) { sKptr[tid] = g_Kptr[tid]; sOrd[tid] = g_order[tid];
                    sInv[tid] = g_invdeg[tid]; sRhs[tid] = g_rhsc[tid];
                    sWoff[tid] = g_woff[tid]; }
    if (tid < NU/2) sNit[tid] = g_Nit[tid];
    if (tid <= NU) { sLptr[tid] = g_Lptr[tid]; sLvl[tid] = g_lvlptr[tid]; }
    if (tid == 0) s_nlev = g_nlev[0];

    // ---- STS batch 1, then batch 2 ----
    if (kn) {
        #pragma unroll
        for (int q = 0; q < 8; q++) sx2[tid*SROW2 + q] = make_float2(v[2*q], v[2*q+1]);
        #pragma unroll
        for (int q = 0; q < 16; q++) v[q] = xb[(size_t)(16+q)*NN + tid];
        #pragma unroll
        for (int q = 0; q < 8; q++) sx2[tid*SROW2 + 8 + q] = make_float2(v[2*q], v[2*q+1]);
    }
    if (tid < SROW2) sx2[DUMMY + tid] = make_float2(0.f, 0.f);
    asm volatile("cp.async.wait_group 0;" ::: "memory");
    __syncthreads();

    const ull* sxp = ((const ull*)sx2) + pl;

    // ---- rhs gather: half-warp = one unknown; striped pairs; idx prefetch --
    #pragma unroll 1
    for (int ii = 0; ii < 4; ii++) {
        int j = w + (ii << 5);           // striped pair assignment 0..127
        int i = (j << 1) + h2;           // unknown
        const uint2* ip = (const uint2*)(sKoff + sKptr[i]);
        int nIt = sNit[j];               // >= 1 by construction
        ull a0 = 0, a1 = 0, a2 = 0, a3 = 0;
        uint2 pk = ip[0];
        #pragma unroll 2
        for (int q = 0; q < nIt; q++) {
            uint2 nk = ip[q+1];          // prefetch (last read is in-bounds slack)
            fadd2(a0, sxp[pk.x & 0xFFFFu]);
            fadd2(a1, sxp[pk.x >> 16]);
            fadd2(a2, sxp[pk.y & 0xFFFFu]);
            fadd2(a3, sxp[pk.y >> 16]);
            pk = nk;
        }
        fadd2(a0, a1); fadd2(a2, a3); fadd2(a0, a2);
        float tx, ty;
        asm("mov.b64 {%0, %1}, %2;" : "=f"(tx), "=f"(ty) : "l"(a0));
        float inv = sInv[i], rh = sRhs[i];
        float2 r; r.x = fmaf(tx, inv, rh); r.y = fmaf(ty, inv, rh);
        sx2[sWoff[i] + pl] = r;
    }
    __syncthreads();

    // ---- level-scheduled solve (in place, half-warp per entry) ----
    int nlev = s_nlev;
    int hg = (w << 1) | h2;              // half-warp id 0..63
    for (int lev = 1; lev < nlev; lev++) {
        int s1 = sLvl[lev+1];
        for (int sl = sLvl[lev] + hg; sl < s1; sl += 64) {
            int i = sOrd[sl];
            int a = sLptr[i];
            int nIt = (sLptr[i+1] - a) >> 2;
            const uint2* ip = (const uint2*)(sLoff + a);
            ull a0 = 0, a1 = 0;
            uint2 pk = ip[0];
            for (int q = 0; q < nIt; q++) {
                uint2 nk = ip[q+1];
                fadd2(a0, sxp[pk.x & 0xFFFFu]);
                fadd2(a1, sxp[pk.x >> 16]);
                fadd2(a0, sxp[pk.y & 0xFFFFu]);
                fadd2(a1, sxp[pk.y >> 16]);
                pk = nk;
            }
            fadd2(a0, a1);
            float tx, ty;
            asm("mov.b64 {%0, %1}, %2;" : "=f"(tx), "=f"(ty) : "l"(a0));
            float inv = sInv[i];
            float2 c = sx2[sWoff[i] + pl];
            c.x = fmaf(tx, inv, c.x); c.y = fmaf(ty, inv, c.y);
            sx2[sWoff[i] + pl] = c;
        }
        __syncthreads();
    }

    // ---- copy out: full tile, perfectly coalesced rows ----
    #pragma unroll
    for (int q = 0; q < 16; q++) {
        float2 t2 = sx2[tid*SROW2 + q];
        ob[(size_t)(2*q)*NN + tid]   = t2.x;
        ob[(size_t)(2*q+1)*NN + tid] = t2.y;
    }
}

// ---------------- launch ----------------
extern "C" void kernel_launch(void* const* d_in, const int* in_sizes, int n_in,
                              void* d_out, int out_size) {
    const float* x    = (const float*)d_in[0];
    const float* A    = (const float*)d_in[1];
    const int*   unk  = (const int*)  d_in[2];
    const float* mask = (const float*)d_in[3];
    float* out = (float*)d_out;

    const int SMEM = (((NN+1)*SROW2*8 + 15) & ~15)
                   + KCAP*2 + LCAP*2
                   + NU*4 + (NU/2)*4 + (NU+1)*4 + NU*4
                   + (NU+1)*4 + NU*4*3 + 32;   // +32 slack

    static void* s_kp_src = nullptr;
    static bool attr_done = false;
    if (!attr_done) {
        cudaFuncSetAttribute(k_fused, cudaFuncAttributeMaxDynamicSharedMemorySize, SMEM);
        cudaGetSymbolAddress(&s_kp_src, g_kp);
        attr_done = true;
    }

    k_row  <<<NU, 256>>>(A, unk);              // launch 0
    k_meta <<<1, 1024>>>(unk, mask);           // launch 1
    cudaMemcpyToSymbolAsync(c_kp, s_kp_src, sizeof(KPack), 0,
                            cudaMemcpyDeviceToDevice, 0);
    k_fused<<<NP/PTS, TPB, SMEM>>>(x, out);    // launch 2
}

// round 14
// speedup vs baseline: 1.0446x; 1.0446x over previous
#include <cuda_runtime.h>

// Problem constants
#define NB 8
#define NT 4096
#define NN 1024
#define NP (NB*NT)      // 32768 points
#define NU 256          // unknown nodes
#define NKMAX 768
#define PTS 32          // points per fused block
#define TPB 1024
#define SROW2 17        // float2 stride per column (32 pts = 16 float2 + 1 pad)
#define DUMMY (NN*SROW2)   // float2-index of zeroed dummy column (fits u16)
#define KCAP 12288      // compact known-CSR cap (u16), pair-padded
#define LCAP 3072       // compact lower-CSR cap (u16), padded to 4

typedef unsigned char  u8;
typedef unsigned short u16;
typedef unsigned int   u32;
typedef unsigned long long ull;

__device__ __forceinline__ void fadd2(ull& a, ull b) {
    asm("add.rn.f32x2 %0, %0, %1;" : "+l"(a) : "l"(b));
}

// ---------------- scratch (device globals; allocation-free) ----------------
__device__ float g_invdeg[NU];
__device__ float g_c[NU];
__device__ int   g_Kcol[NU*NKMAX];
__device__ int   g_Kcnt[NU];
__device__ int   g_Lcol[NU*NU];
__device__ int   g_Lcnt[NU];
__device__ __align__(16) u16 g_Kc[KCAP];   // col*17, dummy-padded
__device__ __align__(16) u16 g_Lc[LCAP];   // unk[rank]*17, dummy-padded
__device__ int   g_Kptr[NU];
__device__ int   g_Nit[NU/2];     // gather iterations (of 4 elems) per pair
__device__ int   g_Lptr[NU+1];
__device__ int   g_Ktot, g_Ltot;
__device__ float g_rhsc[NU];
__device__ int   g_woff[NU];      // unk[i]*17
__device__ int   g_order[NU];
__device__ int   g_lvlptr[NU+1];
__device__ int   g_nlev[1];
__device__ u8    g_knownb[NN];    // 1 if column is known

// ---------------- launch 0: per-row: deg + padded CSR + c ------------------
// 256 blocks x 256 threads; 8-warp two-pass deterministic compaction.
__global__ void k_row(const float* __restrict__ A, const int* __restrict__ unk) {
    __shared__ float srow[NN];
    __shared__ int   srank[NN];
    __shared__ int   wkc[8], wlc[8], wkoff[8], wloff[8];
    __shared__ float wcc[8], wdd[8];
    int i = blockIdx.x, t = threadIdx.x, w = t >> 5, lane = t & 31;
    for (int n = t; n < NN; n += 256) srank[n] = -1;
    __syncthreads();
    srank[__ldg(&unk[t])] = t;          // t = 0..255 = NU
    int ui = __ldg(&unk[i]);
    const float* row = A + (size_t)ui * NN;
    for (int n = t; n < NN; n += 256) srow[n] = row[n];
    __syncthreads();
    unsigned lt = (1u << lane) - 1u;
    int base0 = w * 128;
    // ---- pass 1: counts + exact sums ----
    int kc = 0, lc = 0; float c = 0.f, d = 0.f;
    #pragma unroll
    for (int r = 0; r < 4; r++) {
        int n = base0 + r*32 + lane;
        float a = srow[n];
        int rk = srank[n];
        bool nz = (a != 0.f);
        d += a;
        unsigned mK = __ballot_sync(0xFFFFFFFFu, nz && rk < 0);
        unsigned mL = __ballot_sync(0xFFFFFFFFu, nz && rk >= 0 && rk < i);
        if (nz && rk >= i) c += a;
        kc += __popc(mK); lc += __popc(mL);
    }
    for (int o = 16; o > 0; o >>= 1) {
        c += __shfl_down_sync(0xFFFFFFFFu, c, o);
        d += __shfl_down_sync(0xFFFFFFFFu, d, o);
    }
    if (lane == 0) { wkc[w] = kc; wlc[w] = lc; wcc[w] = c; wdd[w] = d; }
    __syncthreads();
    if (t == 0) {
        int ka = 0, la = 0; float cc = 0.f, dd = 0.f;
        #pragma unroll
        for (int j = 0; j < 8; j++) {
            wkoff[j] = ka; ka += wkc[j];
            wloff[j] = la; la += wlc[j];
            cc += wcc[j]; dd += wdd[j];       // sums of 0/1: exact, order-free
        }
        g_Kcnt[i] = ka; g_Lcnt[i] = la; g_c[i] = cc;
        g_invdeg[i] = 1.f / dd;
    }
    __syncthreads();
    // ---- pass 2: write with stitched offsets (ascending n preserved) ----
    kc = wkoff[w]; lc = wloff[w];
    #pragma unroll
    for (int r = 0; r < 4; r++) {
        int n = base0 + r*32 + lane;
        float a = srow[n];
        int rk = srank[n];
        bool nz = (a != 0.f);
        unsigned mK = __ballot_sync(0xFFFFFFFFu, nz && rk < 0);
        unsigned mL = __ballot_sync(0xFFFFFFFFu, nz && rk >= 0 && rk < i);
        if (nz) {
            if (rk < 0)      g_Kcol[i*NKMAX + kc + __popc(mK & lt)] = n;
            else if (rk < i) g_Lcol[i*NU    + lc + __popc(mL & lt)] = rk;
        }
        kc += __popc(mK); lc += __popc(mL);
    }
}

// ---------------- launch 1: compact + constants + levels (parallel) --------
__global__ void k_meta(const int* __restrict__ unk, const float* __restrict__ maskp) {
    __shared__ int skcnt[NU], slcnt[NU], sunk[NU];
    __shared__ int pairLen[NU/2], scanA[NU], lp4[NU];
    __shared__ int kptr[NU], lptr[NU+1];
    __shared__ u16 slrank[LCAP];
    __shared__ int lev[NU];
    __shared__ u8  knb[NN];
    __shared__ int changed, smax;
    __shared__ int wsum[8], wsum2[8];
    int t = threadIdx.x, w = t >> 5, lane = t & 31;   // 1024 threads
    knb[t] = 1;
    if (t < NU) { skcnt[t] = g_Kcnt[t]; slcnt[t] = g_Lcnt[t]; sunk[t] = unk[t]; }
    __syncthreads();
    if (t < NU) knb[sunk[t]] = 0;
    __syncthreads();
    g_knownb[t] = knb[t];
    if (t < NU/2) {
        int m = skcnt[2*t] > skcnt[2*t+1] ? skcnt[2*t] : skcnt[2*t+1];
        m = (m + 3) & ~3;
        pairLen[t] = m < 4 ? 4 : m;     // min one quad: prefetch-safe
    }
    if (t < NU) {
        int m = (slcnt[t] + 3) & ~3;
        lp4[t] = m < 4 ? 4 : m;
    }
    __syncthreads();
    // ---- inclusive scan of pairLen (n=128) via shuffles ----
    {
        int sv = 0;
        if (t < 128) {
            sv = pairLen[t];
            #pragma unroll
            for (int off = 1; off < 32; off <<= 1) {
                int u = __shfl_up_sync(0xFFFFFFFFu, sv, off);
                if (lane >= off) sv += u;
            }
            if (lane == 31) wsum[w] = sv;
        }
        __syncthreads();
        if (t < 128) {
            int add = 0;
            for (int j = 0; j < w; j++) add += wsum[j];
            scanA[t] = sv + add;
        }
        __syncthreads();
    }
    if (t < NU) {
        int j = t >> 1;
        kptr[t] = 2*(scanA[j] - pairLen[j]) + (t & 1)*pairLen[j];
    }
    if (t == 0) g_Ktot = 2*scanA[NU/2-1] < KCAP ? 2*scanA[NU/2-1] : KCAP;
    __syncthreads();
    // ---- inclusive scan of lp4 (n=256) via shuffles ----
    {
        int sv = 0;
        if (t < NU) {
            sv = lp4[t];
            #pragma unroll
            for (int off = 1; off < 32; off <<= 1) {
                int u = __shfl_up_sync(0xFFFFFFFFu, sv, off);
                if (lane >= off) sv += u;
            }
            if (lane == 31) wsum2[w] = sv;
        }
        __syncthreads();
        if (t < NU) {
            int add = 0;
            for (int j = 0; j < w; j++) add += wsum2[j];
            scanA[t] = sv + add;
        }
        __syncthreads();
    }
    if (t < NU) lptr[t] = scanA[t] - lp4[t];
    if (t == 0) {
        lptr[NU] = scanA[NU-1];
        g_Ltot = scanA[NU-1] < LCAP ? scanA[NU-1] : LCAP;
    }
    __syncthreads();
    // ---- compaction: warp per unknown ----
    for (int ii = 0; ii < 8; ii++) {
        int i = w + 32*ii;
        int kb = kptr[i], kc = skcnt[i], kp = pairLen[i >> 1];
        for (int s = lane; s < kp; s += 32) {
            u16 v = (s < kc) ? (u16)(g_Kcol[i*NKMAX + s] * SROW2) : (u16)DUMMY;
            if (kb + s < KCAP) g_Kc[kb + s] = v;
        }
        int lb = lptr[i], lc = slcnt[i], lp = lp4[i];
        for (int s = lane; s < lp; s += 32) {
            u16 v = (u16)DUMMY;
            if (s < lc) {
                int r = g_Lcol[i*NU + s];
                v = (u16)(sunk[r] * SROW2);
                if (lb + s < LCAP) slrank[lb + s] = (u16)r;
            }
            if (lb + s < LCAP) g_Lc[lb + s] = v;
        }
    }
    if (t < NU) {
        g_rhsc[t] = maskp[0] * g_c[t] * g_invdeg[t];
        g_woff[t] = sunk[t] * SROW2;
        g_Kptr[t] = kptr[t];
    }
    if (t < NU/2) g_Nit[t] = pairLen[t] >> 2;
    if (t <= NU) g_Lptr[t] = lptr[t];
    __syncthreads();
    // ---- level fixpoint: 256 threads, named barrier (cheap drain) ----
    if (t < NU) lev[t] = 0;
    __syncthreads();
    if (t < 256) {
        for (int iter = 0; iter < NU; iter++) {
            if (t == 0) changed = 0;
            asm volatile("bar.sync 1, 256;" ::: "memory");
            int nl = 0;
            {
                int b = lptr[t], e = b + slcnt[t];
                if (e > LCAP) e = LCAP;
                for (int s = b; s < e; s++) {
                    int lj = lev[slrank[s]] + 1;
                    nl = nl > lj ? nl : lj;
                }
            }
            asm volatile("bar.sync 1, 256;" ::: "memory");
            if (nl != lev[t]) { lev[t] = nl; changed = 1; }
            asm volatile("bar.sync 1, 256;" ::: "memory");
            if (!changed) break;
        }
    }
    __syncthreads();
    if (t == 0) smax = 0;
    __syncthreads();
    if (t < NU) atomicMax(&smax, lev[t]);
    __syncthreads();
    if (t <= NU) {
        int c = 0;
        for (int j = 0; j < NU; j++) c += (lev[j] < t);
        g_lvlptr[t] = c;
    }
    if (t < NU) {
        int my = lev[t], pos = 0;
        for (int j = 0; j < NU; j++) {
            int lj = lev[j];
            pos += (lj < my) || (lj == my && j < t);
        }
        g_order[pos] = t;
    }
    if (t == 0) g_nlev[0] = smax + 1;
}

// ---------------- launch 2: fused load(known) -> gather -> solve -> copy ---
__global__ void __launch_bounds__(TPB, 1) k_fused(const float* __restrict__ x,
                                                  float* __restrict__ out) {
    extern __shared__ char smraw[];
    float2* sx2   = (float2*)smraw;                      // (NN+1)*17 float2
    char* p = smraw + (((NN+1)*SROW2*sizeof(float2) + 15) & ~15);  // 16B align
    u16*   sKoff = (u16*)p;          p += KCAP*2;        // 16B aligned
    u16*   sLoff = (u16*)p;          p += LCAP*2;
    int*   sKptr = (int*)p;          p += NU*4;
    int*   sNit  = (int*)p;          p += (NU/2)*4;
    int*   sLptr = (int*)p;          p += (NU+1)*4;
    int*   sOrd  = (int*)p;          p += NU*4;
    int*   sLvl  = (int*)p;          p += (NU+1)*4;
    float* sInv  = (float*)p;        p += NU*4;
    float* sRhs  = (float*)p;        p += NU*4;
    int*   sWoff = (int*)p;
    __shared__ int s_nlev;

    int tid = threadIdx.x, lane = tid & 31, w = tid >> 5;
    int h2 = lane >> 4, pl = lane & 15;
    const float* xb = x   + (size_t)blockIdx.x * PTS * NN;
    float*       ob = out + (size_t)blockIdx.x * PTS * NN;

    // ---- scalar gates (issued first; metadata below hides their latency) --
    int kn = g_knownb[tid];
    int ktot = g_Ktot, ltot = g_Ltot;

    // ---- batch-1 x LDGs (longest latency; gated by kn arrival) ----
    float v[16];
    if (kn) {
        #pragma unroll
        for (int q = 0; q < 16; q++) v[q] = xb[(size_t)q*NN + tid];
    }

    // ---- async-stage index arrays (contiguous 16B cp.async) ----
    {
        u32 sk = (u32)__cvta_generic_to_shared(sKoff);
        u32 sl = (u32)__cvta_generic_to_shared(sLoff);
        const char* gk = (const char*)g_Kc;
        const char* gl = (const char*)g_Lc;
        int kb = (ktot*2 + 15) & ~15;
        int lb = (ltot*2 + 15) & ~15;
        for (int o = tid*16; o < kb; o += TPB*16)
            asm volatile("cp.async.ca.shared.global [%0], [%1], 16;"
                         :: "r"(sk + o), "l"(gk + o));
        for (int o = tid*16; o < lb; o += TPB*16)
            asm volatile("cp.async.ca.shared.global [%0], [%1], 16;"
                         :: "r"(sl + o), "l"(gl + o));
        asm volatile("cp.async.commit_group;");
    }
    // ---- scalar metadata (independent; fills the kn-wait shadow) ----
    if (tid < NU) { sKptr[tid] = g_Kptr[tid]; sOrd[tid] = g_order[tid];
                    sInv[tid] = g_invdeg[tid]; sRhs[tid] = g_rhsc[tid];
                    sWoff[tid] = g_woff[tid]; }
    if (tid < NU/2) sNit[tid] = g_Nit[tid];
    if (tid <= NU) { sLptr[tid] = g_Lptr[tid]; sLvl[tid] = g_lvlptr[tid]; }
    if (tid == 0) s_nlev = g_nlev[0];

    // ---- STS batch 1, then batch 2 ----
    if (kn) {
        #pragma unroll
        for (int q = 0; q < 8; q++) sx2[tid*SROW2 + q] = make_float2(v[2*q], v[2*q+1]);
        #pragma unroll
        for (int q = 0; q < 16; q++) v[q] = xb[(size_t)(16+q)*NN + tid];
        #pragma unroll
        for (int q = 0; q < 8; q++) sx2[tid*SROW2 + 8 + q] = make_float2(v[2*q], v[2*q+1]);
    }
    if (tid < SROW2) sx2[DUMMY + tid] = make_float2(0.f, 0.f);
    asm volatile("cp.async.wait_group 0;" ::: "memory");
    __syncthreads();

    const ull* sxp = ((const ull*)sx2) + pl;

    // ---- rhs gather: half-warp = one unknown; striped pairs; idx prefetch --
    #pragma unroll 1
    for (int ii = 0; ii < 4; ii++) {
        int j = w + (ii << 5);           // striped pair assignment 0..127
        int i = (j << 1) + h2;           // unknown
        const uint2* ip = (const uint2*)(sKoff + sKptr[i]);
        int nIt = sNit[j];               // >= 1 by construction
        ull a0 = 0, a1 = 0, a2 = 0, a3 = 0;
        uint2 pk = ip[0];
        #pragma unroll 2
        for (int q = 0; q < nIt; q++) {
            uint2 nk = ip[q+1];          // prefetch (last read is in-bounds slack)
            fadd2(a0, sxp[pk.x & 0xFFFFu]);
            fadd2(a1, sxp[pk.x >> 16]);
            fadd2(a2, sxp[pk.y & 0xFFFFu]);
            fadd2(a3, sxp[pk.y >> 16]);
            pk = nk;
        }
        fadd2(a0, a1); fadd2(a2, a3); fadd2(a0, a2);
        float tx, ty;
        asm("mov.b64 {%0, %1}, %2;" : "=f"(tx), "=f"(ty) : "l"(a0));
        float inv = sInv[i], rh = sRhs[i];
        float2 r; r.x = fmaf(tx, inv, rh); r.y = fmaf(ty, inv, rh);
        sx2[sWoff[i] + pl] = r;
    }
    __syncthreads();

    // ---- level-scheduled solve on warps 0-15 (512-thread named barrier) ---
    if (tid < 512) {
        int nlev = s_nlev;
        int hg = (w << 1) | h2;          // group id 0..31
        for (int lev = 1; lev < nlev; lev++) {
            int s1 = sLvl[lev+1];
            for (int sl = sLvl[lev] + hg; sl < s1; sl += 32) {
                int i = sOrd[sl];
                int a = sLptr[i];
                int nIt = (sLptr[i+1] - a) >> 2;
                const uint2* ip = (const uint2*)(sLoff + a);
                ull a0 = 0, a1 = 0;
                uint2 pk = ip[0];
                for (int q = 0; q < nIt; q++) {
                    uint2 nk = ip[q+1];
                    fadd2(a0, sxp[pk.x & 0xFFFFu]);
                    fadd2(a1, sxp[pk.x >> 16]);
                    fadd2(a0, sxp[pk.y & 0xFFFFu]);
                    fadd2(a1, sxp[pk.y >> 16]);
                    pk = nk;
                }
                fadd2(a0, a1);
                float tx, ty;
                asm("mov.b64 {%0, %1}, %2;" : "=f"(tx), "=f"(ty) : "l"(a0));
                float inv = sInv[i];
                float2 c = sx2[sWoff[i] + pl];
                c.x = fmaf(tx, inv, c.x); c.y = fmaf(ty, inv, c.y);
                sx2[sWoff[i] + pl] = c;
            }
            asm volatile("bar.sync 1, 512;" ::: "memory");
        }
    }
    __syncthreads();

    // ---- copy out: full tile, perfectly coalesced rows ----
    #pragma unroll
    for (int q = 0; q < 16; q++) {
        float2 t2 = sx2[tid*SROW2 + q];
        ob[(size_t)(2*q)*NN + tid]   = t2.x;
        ob[(size_t)(2*q+1)*NN + tid] = t2.y;
    }
}

// ---------------- launch ----------------
extern "C" void kernel_launch(void* const* d_in, const int* in_sizes, int n_in,
                              void* d_out, int out_size) {
    const float* x    = (const float*)d_in[0];
    const float* A    = (const float*)d_in[1];
    const int*   unk  = (const int*)  d_in[2];
    const float* mask = (const float*)d_in[3];
    float* out = (float*)d_out;

    const int SMEM = (((NN+1)*SROW2*8 + 15) & ~15)
                   + KCAP*2 + LCAP*2
                   + NU*4 + (NU/2)*4 + (NU+1)*4 + NU*4
                   + (NU+1)*4 + NU*4*3 + 32;   // +32 slack

    static bool attr_done = false;
    if (!attr_done) {
        cudaFuncSetAttribute(k_fused, cudaFuncAttributeMaxDynamicSharedMemorySize, SMEM);
        attr_done = true;
    }

    k_row  <<<NU, 256>>>(A, unk);              // launch 0
    k_meta <<<1, 1024>>>(unk, mask);           // launch 1
    k_fused<<<NP/PTS, TPB, SMEM>>>(x, out);    // launch 2
}